// round 16
// baseline (speedup 1.0000x reference)
#include <cuda_runtime.h>
#include <math.h>
#include <stdint.h>

// ---------------------------------------------------------------------------
// WindowAttention fused kernel, round 16 (base R15):
//  final projection on ALL 8 warps (M=32 x N=24): Sa packed (conversion-free),
//  B-frag reuse preserved, per-warp HMMA halves vs R15's 4-warp proj.
// ---------------------------------------------------------------------------

#define NTOK   49
#define NCH    96
#define NHEADS 3
#define HDIM   32
#define ST     100
#define PST    50
#define AST    50
#define CST    34
#define SCALEF 0.17677669529663687f
#define NTHR   256

#define BUF     (NTOK*ST)
#define OFF_A   0
#define OFF_B   (OFF_A + BUF)
#define OFF_C   (OFF_B + BUF)
#define OFF_D   (OFF_C + BUF)
#define OFF_RPB (OFF_D + BUF)
#define OFF_NQ  (OFF_RPB + 508)
#define OFF_NK  (OFF_NQ + 96)
#define OFF_E   (OFF_NK + 96)
#define OFF_CAT (OFF_E + BUF)
#define SMEM_FLOATS (OFF_CAT + 3264)
#define SMEM_BYTES  (SMEM_FLOATS * 4)

#define SCRH    2450

#define FRAG_PER_G 2304
#define PROJ_FBASE (7 * FRAG_PER_G)
#define NFRAG      (PROJ_FBASE + 12 * 12 * 32)

__device__ uint4 g_wpack[NFRAG];

typedef unsigned long long u64;

__device__ __forceinline__ void fma2(u64& d, u64 a, u64 b) {
    asm("fma.rn.f32x2 %0,%1,%2,%0;" : "+l"(d) : "l"(a), "l"(b));
}
__device__ __forceinline__ float2 unp(u64 a) {
    float2 r; asm("mov.b64 {%0,%1},%2;" : "=f"(r.x), "=f"(r.y) : "l"(a)); return r;
}
__device__ __forceinline__ u64 lds64(const float* p) {
    return *reinterpret_cast<const u64*>(p);
}
__device__ __forceinline__ uint32_t cvtbf2(float h, float l) {
    uint32_t r; asm("cvt.rn.bf16x2.f32 %0, %1, %2;" : "=r"(r) : "f"(h), "f"(l)); return r;
}
__device__ __forceinline__ float blo2f(uint32_t p) { return __uint_as_float(p << 16); }
__device__ __forceinline__ float bhi2f(uint32_t p) { return __uint_as_float(p & 0xFFFF0000u); }

__device__ __forceinline__ void mma16(float d[4],
                                      uint32_t a0, uint32_t a1, uint32_t a2, uint32_t a3,
                                      uint32_t b0, uint32_t b1) {
    asm volatile("mma.sync.aligned.m16n8k16.row.col.f32.bf16.bf16.f32 "
                 "{%0,%1,%2,%3}, {%4,%5,%6,%7}, {%8,%9}, {%0,%1,%2,%3};"
                 : "+f"(d[0]), "+f"(d[1]), "+f"(d[2]), "+f"(d[3])
                 : "r"(a0), "r"(a1), "r"(a2), "r"(a3), "r"(b0), "r"(b1));
}

__device__ __forceinline__ void split2(float2 p, uint32_t& h, uint32_t& l) {
    h = cvtbf2(p.y, p.x);
    l = cvtbf2(p.y - bhi2f(h), p.x - blo2f(h));
}

// ---------------- prologue: pack weight B-fragments in warp order -----------
__global__ void prep_weights(const float* __restrict__ wq, const float* __restrict__ wk,
                             const float* __restrict__ wv, const float* __restrict__ w_ps,
                             const float* __restrict__ wq_sp, const float* __restrict__ wk_sp,
                             const float* __restrict__ w_pc, const float* __restrict__ w_proj)
{
    int idx = blockIdx.x * 256 + threadIdx.x;
    if (idx >= NFRAG) return;
    const float* Wt[8] = {wq, wk, wv, w_ps, wq_sp, wk_sp, w_pc, w_proj};
    int g, r;
    if (idx < PROJ_FBASE) { g = idx / FRAG_PER_G; r = idx % FRAG_PER_G; }
    else                  { g = 7; r = idx - PROJ_FBASE; }
    int kc   = r / 384;
    int rem  = r % 384;
    int slot = rem / 32;
    int lane = rem % 32;
    int gid = lane >> 2, tig = lane & 3;
    int kp = kc * 8 + tig;
    int n  = slot * 8 + gid;
    const float* W = Wt[g];
    float x0 = W[(2 * kp) * 96 + n];
    float x1 = W[(2 * kp + 1) * 96 + n];
    float y0 = W[(2 * kp + 8) * 96 + n];
    float y1 = W[(2 * kp + 9) * 96 + n];
    uint32_t b0h, b0l, b1h, b1l;
    split2(make_float2(x0, x1), b0h, b0l);
    split2(make_float2(y0, y1), b1h, b1l);
    g_wpack[idx] = make_uint4(b0h, b1h, b0l, b1l);
}

// ---- gemm2s: pre-split A, M=32 x N=48 per slot ------------------------------
__device__ __forceinline__ void gemm2s(const uint32_t* Ah, const uint32_t* Al, int fbase,
                                       const float* __restrict__ bias,
                                       float* Os, uint32_t* Oh, uint32_t* Ol,
                                       int sub, int lane, int splitout)
{
    const int m0 = (sub >> 1) * 32;
    const int nh = sub & 1, n0 = nh * 48;
    const int gid = lane >> 2, tig = lane & 3;
    float d[2][6][4];
    #pragma unroll
    for (int m = 0; m < 2; m++)
        #pragma unroll
        for (int i = 0; i < 6; i++) { d[m][i][0] = d[m][i][1] = d[m][i][2] = d[m][i][3] = 0.f; }
    const int r0b = (m0 + gid) * PST, r1b = (m0 + gid + 8) * PST;
    const int r2b = (m0 + gid + 16) * PST, r3b = (m0 + gid + 24) * PST;
    #pragma unroll
    for (int kc = 0; kc < 6; kc++) {
        const int kp = kc * 8 + tig;
        uint32_t ah[2][4], al[2][4];
        ah[0][0] = Ah[r0b + kp];     al[0][0] = Al[r0b + kp];
        ah[0][1] = Ah[r1b + kp];     al[0][1] = Al[r1b + kp];
        ah[0][2] = Ah[r0b + kp + 4]; al[0][2] = Al[r0b + kp + 4];
        ah[0][3] = Ah[r1b + kp + 4]; al[0][3] = Al[r1b + kp + 4];
        ah[1][0] = Ah[r2b + kp];     al[1][0] = Al[r2b + kp];
        ah[1][1] = Ah[r3b + kp];     al[1][1] = Al[r3b + kp];
        ah[1][2] = Ah[r2b + kp + 4]; al[1][2] = Al[r2b + kp + 4];
        ah[1][3] = Ah[r3b + kp + 4]; al[1][3] = Al[r3b + kp + 4];
        const uint4* Bf = g_wpack + fbase + (kc * 12 + nh * 6) * 32 + lane;
        #pragma unroll
        for (int nt = 0; nt < 6; nt++) {
            uint4 w = Bf[nt * 32];
            #pragma unroll
            for (int m = 0; m < 2; m++) {
                mma16(d[m][nt], ah[m][0], ah[m][1], ah[m][2], ah[m][3], w.x, w.y);
                mma16(d[m][nt], ah[m][0], ah[m][1], ah[m][2], ah[m][3], w.z, w.w);
                mma16(d[m][nt], al[m][0], al[m][1], al[m][2], al[m][3], w.x, w.y);
            }
        }
    }
    #pragma unroll
    for (int m = 0; m < 2; m++) {
        const int r0 = m0 + m * 16 + gid, r1 = r0 + 8;
        #pragma unroll
        for (int nt = 0; nt < 6; nt++) {
            int n = n0 + nt * 8 + tig * 2;
            float bx = 0.f, by = 0.f;
            if (bias) { bx = bias[n]; by = bias[n + 1]; }
            if (splitout) {
                int w = n >> 1;
                if (r0 < NTOK) {
                    uint32_t h, l;
                    split2(make_float2(d[m][nt][0] + bx, d[m][nt][1] + by), h, l);
                    Oh[r0 * PST + w] = h; Ol[r0 * PST + w] = l;
                }
                if (r1 < NTOK) {
                    uint32_t h, l;
                    split2(make_float2(d[m][nt][2] + bx, d[m][nt][3] + by), h, l);
                    Oh[r1 * PST + w] = h; Ol[r1 * PST + w] = l;
                }
            } else {
                if (r0 < NTOK) { float* o = Os + r0 * ST + n; o[0] = d[m][nt][0] + bx; o[1] = d[m][nt][1] + by; }
                if (r1 < NTOK) { float* o = Os + r1 * ST + n; o[0] = d[m][nt][2] + bx; o[1] = d[m][nt][3] + by; }
            }
        }
    }
}

// ---- gemm_s8: pre-split A, 8 warps, M=16 tiles (ks, out_c) -----------------
__device__ __forceinline__ void gemm_s8(const uint32_t* Ah, const uint32_t* Al, int fbase,
                                        const float* __restrict__ bias, float* Os,
                                        int warp, int lane)
{
    const int m0 = (warp >> 1) * 16;
    const int nh = warp & 1, n0 = nh * 48;
    const int gid = lane >> 2, tig = lane & 3;
    float d[6][4];
    #pragma unroll
    for (int i = 0; i < 6; i++) { d[i][0] = d[i][1] = d[i][2] = d[i][3] = 0.f; }
    const int r0b = (m0 + gid) * PST, r1b = (m0 + gid + 8) * PST;
    #pragma unroll
    for (int kc = 0; kc < 6; kc++) {
        const int kp = kc * 8 + tig;
        uint32_t a0h = Ah[r0b + kp],     a0l = Al[r0b + kp];
        uint32_t a1h = Ah[r1b + kp],     a1l = Al[r1b + kp];
        uint32_t a2h = Ah[r0b + kp + 4], a2l = Al[r0b + kp + 4];
        uint32_t a3h = Ah[r1b + kp + 4], a3l = Al[r1b + kp + 4];
        const uint4* Bf = g_wpack + fbase + (kc * 12 + nh * 6) * 32 + lane;
        #pragma unroll
        for (int nt = 0; nt < 6; nt++) {
            uint4 w = Bf[nt * 32];
            mma16(d[nt], a0h, a1h, a2h, a3h, w.x, w.y);
            mma16(d[nt], a0h, a1h, a2h, a3h, w.z, w.w);
            mma16(d[nt], a0l, a1l, a2l, a3l, w.x, w.y);
        }
    }
    const int r0 = m0 + gid, r1 = m0 + gid + 8;
    #pragma unroll
    for (int nt = 0; nt < 6; nt++) {
        int n = n0 + nt * 8 + tig * 2;
        float bx = 0.f, by = 0.f;
        if (bias) { bx = bias[n]; by = bias[n + 1]; }
        if (r0 < NTOK) { float* o = Os + r0 * ST + n; o[0] = d[nt][0] + bx; o[1] = d[nt][1] + by; }
        if (r1 < NTOK) { float* o = Os + r1 * ST + n; o[0] = d[nt][2] + bx; o[1] = d[nt][3] + by; }
    }
}

// ---- final projection: 8 warps, M=32 x N=24; Sa PACKED, Sb fp32 ------------
__device__ __forceinline__ void proj8s(const uint32_t* Sh, const uint32_t* Sl,
                                       const float* Sb,
                                       const float* __restrict__ bias,
                                       float* __restrict__ og, int warp, int lane)
{
    const int m0 = (warp >> 2) * 32;          // 2 m-halves
    const int nh = warp & 3, n0 = nh * 24;    // 4 n-quarters, 3 nt each
    const int gid = lane >> 2, tig = lane & 3;
    float d[2][3][4];
    #pragma unroll
    for (int m = 0; m < 2; m++)
        #pragma unroll
        for (int i = 0; i < 3; i++) { d[m][i][0] = d[m][i][1] = d[m][i][2] = d[m][i][3] = 0.f; }
    #pragma unroll
    for (int kc = 0; kc < 12; kc++) {
        const int kp = (kc % 6) * 8 + tig;
        uint32_t ah[2][4], al[2][4];
        if (kc < 6) {
            const int r0b = (m0 + gid) * PST, r1b = r0b + 8 * PST;
            const int r2b = r0b + 16 * PST, r3b = r0b + 24 * PST;
            ah[0][0] = Sh[r0b + kp];     al[0][0] = Sl[r0b + kp];
            ah[0][1] = Sh[r1b + kp];     al[0][1] = Sl[r1b + kp];
            ah[0][2] = Sh[r0b + kp + 4]; al[0][2] = Sl[r0b + kp + 4];
            ah[0][3] = Sh[r1b + kp + 4]; al[0][3] = Sl[r1b + kp + 4];
            ah[1][0] = Sh[r2b + kp];     al[1][0] = Sl[r2b + kp];
            ah[1][1] = Sh[r3b + kp];     al[1][1] = Sl[r3b + kp];
            ah[1][2] = Sh[r2b + kp + 4]; al[1][2] = Sl[r2b + kp + 4];
            ah[1][3] = Sh[r3b + kp + 4]; al[1][3] = Sl[r3b + kp + 4];
        } else {
            const float* X0 = Sb + (m0 + gid) * ST;
            const float* X1 = X0 + 8 * ST;
            const float* X2 = X0 + 16 * ST;
            const float* X3 = X0 + 24 * ST;
            split2(*reinterpret_cast<const float2*>(X0 + 2 * kp),     ah[0][0], al[0][0]);
            split2(*reinterpret_cast<const float2*>(X1 + 2 * kp),     ah[0][1], al[0][1]);
            split2(*reinterpret_cast<const float2*>(X0 + 2 * kp + 8), ah[0][2], al[0][2]);
            split2(*reinterpret_cast<const float2*>(X1 + 2 * kp + 8), ah[0][3], al[0][3]);
            split2(*reinterpret_cast<const float2*>(X2 + 2 * kp),     ah[1][0], al[1][0]);
            split2(*reinterpret_cast<const float2*>(X3 + 2 * kp),     ah[1][1], al[1][1]);
            split2(*reinterpret_cast<const float2*>(X2 + 2 * kp + 8), ah[1][2], al[1][2]);
            split2(*reinterpret_cast<const float2*>(X3 + 2 * kp + 8), ah[1][3], al[1][3]);
        }
        const uint4* Bf = g_wpack + PROJ_FBASE + (kc * 12 + nh * 3) * 32 + lane;
        #pragma unroll
        for (int nt = 0; nt < 3; nt++) {
            uint4 w = Bf[nt * 32];
            #pragma unroll
            for (int m = 0; m < 2; m++) {
                mma16(d[m][nt], ah[m][0], ah[m][1], ah[m][2], ah[m][3], w.x, w.y);
                mma16(d[m][nt], ah[m][0], ah[m][1], ah[m][2], ah[m][3], w.z, w.w);
                mma16(d[m][nt], al[m][0], al[m][1], al[m][2], al[m][3], w.x, w.y);
            }
        }
    }
    #pragma unroll
    for (int m = 0; m < 2; m++) {
        const int r0 = m0 + m * 16 + gid, r1 = r0 + 8;
        #pragma unroll
        for (int nt = 0; nt < 3; nt++) {
            int n = n0 + nt * 8 + tig * 2;
            float bx = bias[n], by = bias[n + 1];
            if (r0 < NTOK) {
                float2 v = make_float2(d[m][nt][0] + bx, d[m][nt][1] + by);
                *reinterpret_cast<float2*>(og + r0 * NCH + n) = v;
            }
            if (r1 < NTOK) {
                float2 v = make_float2(d[m][nt][2] + bx, d[m][nt][3] + by);
                *reinterpret_cast<float2*>(og + r1 * NCH + n) = v;
            }
        }
    }
}

// ---- scores from PRE-SPLIT q/k ----------------------------------------------
__device__ __forceinline__ void scores_mma_s(const uint32_t* Qh, const uint32_t* Ql,
                                             const uint32_t* Kh, const uint32_t* Kl,
                                             float* SC, const float* RPB,
                                             int slot0, int stride, int lane)
{
    const int gid = lane >> 2, tig = lane & 3;
    for (int slot = slot0; slot < 24; slot += stride) {
        const int h = slot >> 3, q = slot & 7;
        const int m0 = (q >> 1) * 16, n0 = (q & 1) * 32;
        const int cw = h * 16;
        float* SCR = SC + h * SCRH;
        float d[4][4];
        #pragma unroll
        for (int i = 0; i < 4; i++) { d[i][0] = d[i][1] = d[i][2] = d[i][3] = 0.f; }
        const int q0b = (m0 + gid) * PST + cw, q1b = q0b + 8 * PST;
        #pragma unroll
        for (int kc = 0; kc < 2; kc++) {
            const int kp = kc * 8 + tig;
            uint32_t a0h = Qh[q0b + kp],     a0l = Ql[q0b + kp];
            uint32_t a1h = Qh[q1b + kp],     a1l = Ql[q1b + kp];
            uint32_t a2h = Qh[q0b + kp + 4], a2l = Ql[q0b + kp + 4];
            uint32_t a3h = Qh[q1b + kp + 4], a3l = Ql[q1b + kp + 4];
            #pragma unroll
            for (int nt = 0; nt < 4; nt++) {
                const int kb = (n0 + nt * 8 + gid) * PST + cw;
                uint32_t b0h = Kh[kb + kp],     b0l = Kl[kb + kp];
                uint32_t b1h = Kh[kb + kp + 4], b1l = Kl[kb + kp + 4];
                mma16(d[nt], a0h, a1h, a2h, a3h, b0h, b1h);
                mma16(d[nt], a0h, a1h, a2h, a3h, b0l, b1l);
                mma16(d[nt], a0l, a1l, a2l, a3l, b0h, b1h);
            }
        }
        const int r0 = m0 + gid, r1 = r0 + 8;
        const int i0r = r0 / 7, i0c = r0 % 7;
        const int i1r = r1 / 7, i1c = r1 % 7;
        #pragma unroll
        for (int nt = 0; nt < 4; nt++) {
            #pragma unroll
            for (int c = 0; c < 2; c++) {
                int j = n0 + nt * 8 + tig * 2 + c;
                if (j < NTOK) {
                    int jr = j / 7, jc = j % 7;
                    if (r0 < NTOK)
                        SCR[r0 * AST + j] = d[nt][c] * SCALEF
                            + RPB[((i0r - jr + 6) * 13 + (i0c - jc + 6)) * 3 + h];
                    if (r1 < NTOK)
                        SCR[r1 * AST + j] = d[nt][2 + c] * SCALEF
                            + RPB[((i1r - jr + 6) * 13 + (i1c - jc + 6)) * 3 + h];
                }
            }
        }
    }
}

// ---- attn@V from PRE-SPLIT P; sp written PRE-SPLIT --------------------------
__device__ __forceinline__ void attnv_ps(const uint32_t* SC32, const float* V,
                                         uint32_t* SPh, uint32_t* SPl,
                                         int warp, int lane)
{
    const int gid = lane >> 2, tig = lane & 3;
    for (int slot = warp; slot < 24; slot += 8) {
        const int h = slot >> 3, q = slot & 7;
        const int m0 = (q >> 1) * 16, n0 = (q & 1) * 16;
        const int ch0 = h * HDIM;
        const uint32_t* Pb = SC32 + h * SCRH;
        float d[2][4];
        #pragma unroll
        for (int i = 0; i < 2; i++) { d[i][0] = d[i][1] = d[i][2] = d[i][3] = 0.f; }
        const int r0w = (m0 + gid) * AST, r1w = r0w + 8 * AST;
        #pragma unroll
        for (int kc = 0; kc < 4; kc++) {
            const int w0 = kc * 8 + tig;
            const int w2 = w0 + 4;
            const int k0 = 2 * w0, k2 = 2 * w2;
            uint32_t a0h = 0, a0l = 0, a1h = 0, a1l = 0;
            uint32_t a2h = 0, a2l = 0, a3h = 0, a3l = 0;
            if (w0 <= 24) {
                a0h = Pb[r0w + w0]; a0l = Pb[r0w + 25 + w0];
                a1h = Pb[r1w + w0]; a1l = Pb[r1w + 25 + w0];
            }
            if (w2 <= 24) {
                a2h = Pb[r0w + w2]; a2l = Pb[r0w + 25 + w2];
                a3h = Pb[r1w + w2]; a3l = Pb[r1w + 25 + w2];
            }
            #pragma unroll
            for (int nt = 0; nt < 2; nt++) {
                const int n = ch0 + n0 + nt * 8 + gid;
                uint32_t b0h, b0l, b1h, b1l;
                split2(make_float2(V[k0 * ST + n], V[(k0 + 1) * ST + n]), b0h, b0l);
                split2(make_float2(V[k2 * ST + n], V[(k2 + 1) * ST + n]), b1h, b1l);
                mma16(d[nt], a0h, a1h, a2h, a3h, b0h, b1h);
                mma16(d[nt], a0h, a1h, a2h, a3h, b0l, b1l);
                mma16(d[nt], a0l, a1l, a2l, a3l, b0h, b1h);
            }
        }
        const int r0 = m0 + gid, r1 = r0 + 8;
        #pragma unroll
        for (int nt = 0; nt < 2; nt++) {
            int n = ch0 + n0 + nt * 8 + tig * 2;
            int w = n >> 1;
            if (r0 < NTOK) {
                uint32_t hh, ll;
                split2(make_float2(d[nt][0], d[nt][1]), hh, ll);
                SPh[r0 * PST + w] = hh; SPl[r0 * PST + w] = ll;
            }
            if (r1 < NTOK) {
                uint32_t hh, ll;
                split2(make_float2(d[nt][2], d[nt][3]), hh, ll);
                SPh[r1 * PST + w] = hh; SPl[r1 * PST + w] = ll;
            }
        }
    }
}

// ---- cattn via MMA (6 warps) ------------------------------------------------
__device__ __forceinline__ void cattn_mma(const float* QS, const float* KS,
                                          float* CAT, const float* NQ, const float* NK,
                                          int warp, int lane)
{
    if (warp >= 6) return;
    const int h = warp >> 1, mt = warp & 1;
    const int ch = h * HDIM, m0 = mt * 16;
    const int gid = lane >> 2, tig = lane & 3;
    float d[4][4];
    #pragma unroll
    for (int i = 0; i < 4; i++) { d[i][0] = d[i][1] = d[i][2] = d[i][3] = 0.f; }
    #pragma unroll
    for (int kc = 0; kc < 4; kc++) {
        const int k0 = 2 * (kc * 8 + tig);
        const int k1 = k0 + 1, k2 = k0 + 8, k3 = k0 + 9;
        const int ca = ch + m0 + gid;
        float a00 = (k0 < NTOK) ? KS[k0 * ST + ca] : 0.f;
        float a01 = (k1 < NTOK) ? KS[k1 * ST + ca] : 0.f;
        float a10 = (k0 < NTOK) ? KS[k0 * ST + ca + 8] : 0.f;
        float a11 = (k1 < NTOK) ? KS[k1 * ST + ca + 8] : 0.f;
        float a20 = (k2 < NTOK) ? KS[k2 * ST + ca] : 0.f;
        float a21 = (k3 < NTOK) ? KS[k3 * ST + ca] : 0.f;
        float a30 = (k2 < NTOK) ? KS[k2 * ST + ca + 8] : 0.f;
        float a31 = (k3 < NTOK) ? KS[k3 * ST + ca + 8] : 0.f;
        uint32_t a0h, a0l, a1h, a1l, a2h, a2l, a3h, a3l;
        split2(make_float2(a00, a01), a0h, a0l);
        split2(make_float2(a10, a11), a1h, a1l);
        split2(make_float2(a20, a21), a2h, a2l);
        split2(make_float2(a30, a31), a3h, a3l);
        #pragma unroll
        for (int nt = 0; nt < 4; nt++) {
            const int ce = ch + nt * 8 + gid;
            float b00 = (k0 < NTOK) ? QS[k0 * ST + ce] : 0.f;
            float b01 = (k1 < NTOK) ? QS[k1 * ST + ce] : 0.f;
            float b10 = (k2 < NTOK) ? QS[k2 * ST + ce] : 0.f;
            float b11 = (k3 < NTOK) ? QS[k3 * ST + ce] : 0.f;
            uint32_t b0h, b0l, b1h, b1l;
            split2(make_float2(b00, b01), b0h, b0l);
            split2(make_float2(b10, b11), b1h, b1l);
            mma16(d[nt], a0h, a1h, a2h, a3h, b0h, b1h);
            mma16(d[nt], a0h, a1h, a2h, a3h, b0l, b1l);
            mma16(d[nt], a0l, a1l, a2l, a3l, b0h, b1h);
        }
    }
    const int r0 = m0 + gid, r1 = r0 + 8;
    const float sk0 = NK[ch + r0] * SCALEF;
    const float sk1 = NK[ch + r1] * SCALEF;
    float* C0 = CAT + h * 1088 + r0 * CST;
    float* C1 = CAT + h * 1088 + r1 * CST;
    #pragma unroll
    for (int nt = 0; nt < 4; nt++) {
        int e0 = nt * 8 + tig * 2;
        float q0 = NQ[ch + e0], q1 = NQ[ch + e0 + 1];
        C0[e0]     = d[nt][0] * sk0 * q0;
        C0[e0 + 1] = d[nt][1] * sk0 * q1;
        C1[e0]     = d[nt][2] * sk1 * q0;
        C1[e0 + 1] = d[nt][3] * sk1 * q1;
    }
}

// ---- xc via MMA, output PRE-SPLIT -------------------------------------------
__device__ __forceinline__ void xc_mma_so(const float* CAT, const float* V,
                                          uint32_t* Oh, uint32_t* Ol,
                                          int warp, int lane)
{
    const int gid = lane >> 2, tig = lane & 3;
    for (int slot = warp; slot < 12; slot += 8) {
        const int h = slot >> 2, mt = slot & 3;
        const int ch = h * HDIM, m0 = mt * 16;
        float d[4][4];
        #pragma unroll
        for (int i = 0; i < 4; i++) { d[i][0] = d[i][1] = d[i][2] = d[i][3] = 0.f; }
        const float* Ar0 = V + (m0 + gid) * ST + ch;
        const float* Ar1 = Ar0 + 8 * ST;
        #pragma unroll
        for (int kc = 0; kc < 2; kc++) {
            const int kp = kc * 8 + tig;
            uint32_t a0h, a0l, a1h, a1l, a2h, a2l, a3h, a3l;
            split2(*reinterpret_cast<const float2*>(Ar0 + 2 * kp), a0h, a0l);
            split2(*reinterpret_cast<const float2*>(Ar1 + 2 * kp), a1h, a1l);
            split2(*reinterpret_cast<const float2*>(Ar0 + 2 * kp + 8), a2h, a2l);
            split2(*reinterpret_cast<const float2*>(Ar1 + 2 * kp + 8), a3h, a3l);
            #pragma unroll
            for (int nt = 0; nt < 4; nt++) {
                const float* Br = CAT + h * 1088 + (nt * 8 + gid) * CST;
                uint32_t b0h, b0l, b1h, b1l;
                split2(*reinterpret_cast<const float2*>(Br + 2 * kp), b0h, b0l);
                split2(*reinterpret_cast<const float2*>(Br + 2 * kp + 8), b1h, b1l);
                mma16(d[nt], a0h, a1h, a2h, a3h, b0h, b1h);
                mma16(d[nt], a0h, a1h, a2h, a3h, b0l, b1l);
                mma16(d[nt], a0l, a1l, a2l, a3l, b0h, b1h);
            }
        }
        const int r0 = m0 + gid, r1 = r0 + 8;
        #pragma unroll
        for (int nt = 0; nt < 4; nt++) {
            int n = ch + nt * 8 + tig * 2;
            int w = n >> 1;
            if (r0 < NTOK) {
                uint32_t hh, ll;
                split2(make_float2(d[nt][0], d[nt][1]), hh, ll);
                Oh[r0 * PST + w] = hh; Ol[r0 * PST + w] = ll;
            }
            if (r1 < NTOK) {
                uint32_t hh, ll;
                split2(make_float2(d[nt][2], d[nt][3]), hh, ll);
                Oh[r1 * PST + w] = hh; Ol[r1 * PST + w] = ll;
            }
        }
    }
}

// ---- depthwise 3x3 conv -----------------------------------------------------
__device__ __forceinline__ void dwconv5(const float* In, const float* __restrict__ Wc,
                                        float* Out, int tid, int mode)
{
    if (tid >= 240) return;
    const int c0 = (tid / 10) * 4, t0 = (tid % 10) * 5;
    u64 wc[9][2];
    #pragma unroll
    for (int s = 0; s < 9; s++) {
        const ulonglong2* wp = reinterpret_cast<const ulonglong2*>(Wc + s * 96 + c0);
        ulonglong2 w = *wp;
        wc[s][0] = w.x; wc[s][1] = w.y;
    }
    #pragma unroll
    for (int tt = 0; tt < 5; tt++) {
        int t = t0 + tt;
        if (t >= NTOK) break;
        int r = t / 7, cc = t % 7;
        u64 a0 = 0ULL, a1 = 0ULL;
        #pragma unroll
        for (int dr = 0; dr < 3; dr++) {
            int rr = r + dr - 1;
            if (rr < 0 || rr > 6) continue;
            #pragma unroll
            for (int dc = 0; dc < 3; dc++) {
                int c2 = cc + dc - 1;
                if (c2 < 0 || c2 > 6) continue;
                const float* vp = In + (rr * 7 + c2) * ST + c0;
                fma2(a0, lds64(vp), wc[dr * 3 + dc][0]);
                fma2(a1, lds64(vp + 2), wc[dr * 3 + dc][1]);
            }
        }
        float2 p0 = unp(a0), p1 = unp(a1);
        float* o = Out + t * ST + c0;
        if (mode == 0) {
            o[0] = 0.5f * p0.x * (1.f + erff(p0.x * 0.70710678118654752f));
            o[1] = 0.5f * p0.y * (1.f + erff(p0.y * 0.70710678118654752f));
            o[2] = 0.5f * p1.x * (1.f + erff(p1.x * 0.70710678118654752f));
            o[3] = 0.5f * p1.y * (1.f + erff(p1.y * 0.70710678118654752f));
        } else {
            o[0] += p0.x; o[1] += p0.y; o[2] += p1.x; o[3] += p1.y;
        }
    }
}

__global__ __launch_bounds__(NTHR, 2) void winattn_kernel(
    const float* __restrict__ x,
    const float* __restrict__ rpb_table,
    const float* __restrict__ bq,  const float* __restrict__ bk,
    const float* __restrict__ bv,  const float* __restrict__ b_ps,
    const float* __restrict__ b_pc,
    const float* __restrict__ conv1, const float* __restrict__ conv2,
    const float* __restrict__ b_proj,
    float* __restrict__ out)
{
    extern __shared__ float sm[];
    uint32_t* Xh = reinterpret_cast<uint32_t*>(sm + OFF_A);
    uint32_t* Xl = Xh + 2450;
    uint32_t* Qh = reinterpret_cast<uint32_t*>(sm + OFF_B);
    uint32_t* Ql = Qh + 2450;
    float*    Bb = sm + OFF_B;
    uint32_t* Kh = reinterpret_cast<uint32_t*>(sm + OFF_C);
    uint32_t* Kl = Kh + 2450;
    float* Dd  = sm + OFF_D;
    float* Ee  = sm + OFF_E;
    uint32_t* SC32 = reinterpret_cast<uint32_t*>(Ee);
    float* RPB = sm + OFF_RPB;
    float* NQ  = sm + OFF_NQ;
    float* NK  = sm + OFF_NK;
    float* CAT = sm + OFF_CAT;

    const int tid  = threadIdx.x;
    const int blk  = blockIdx.x;
    const int warp = tid >> 5, lane = tid & 31;

    {
        const float4* xg4 = reinterpret_cast<const float4*>(x + (size_t)blk * (NTOK * NCH));
        for (int i4 = tid; i4 < NTOK * 24; i4 += NTHR) {
            float4 v = xg4[i4];
            int t = i4 / 24, p = (i4 % 24) * 2;
            uint32_t h0, l0, h1, l1;
            split2(make_float2(v.x, v.y), h0, l0);
            split2(make_float2(v.z, v.w), h1, l1);
            Xh[t * PST + p] = h0;     Xl[t * PST + p] = l0;
            Xh[t * PST + p + 1] = h1; Xl[t * PST + p + 1] = l1;
        }
        for (int i = tid; i < 507; i += NTHR) RPB[i] = rpb_table[i];
    }
    __syncthreads();

    // ---- ph1: {q (w0-3) | k (w4-7)}, split in + SPLIT out ----
    if (warp < 4) gemm2s(Xh, Xl, 0 * FRAG_PER_G, bq, 0, Qh, Ql, warp, lane, 1);
    else          gemm2s(Xh, Xl, 1 * FRAG_PER_G, bk, 0, Kh, Kl, warp - 4, lane, 1);
    __syncthreads();

    // ---- ph2: {v (w0-3, fp32 out) | scores all heads (w4-7)} ----
    if (warp < 4) gemm2s(Xh, Xl, 2 * FRAG_PER_G, bv, Dd, 0, 0, warp, lane, 0);
    else          scores_mma_s(Qh, Ql, Kh, Kl, Ee, RPB, warp - 4, 4, lane);
    __syncthreads();

    // ---- ph3: softmax + in-place P packing ----
    for (int r = warp; r < 3 * NTOK; r += 8) {
        float* row = Ee + (r / NTOK) * SCRH + (r % NTOK) * AST;
        uint32_t* row32 = reinterpret_cast<uint32_t*>(row);
        float e1 = row[lane];
        bool hi = (lane + 32) < NTOK;
        float e2 = hi ? row[lane + 32] : -3.4e38f;
        float m = fmaxf(e1, e2);
        #pragma unroll
        for (int o = 16; o > 0; o >>= 1) m = fmaxf(m, __shfl_xor_sync(0xffffffffu, m, o));
        float p1 = __expf(e1 - m);
        float p2 = hi ? __expf(e2 - m) : 0.f;
        float s = p1 + p2;
        #pragma unroll
        for (int o = 16; o > 0; o >>= 1) s += __shfl_xor_sync(0xffffffffu, s, o);
        float inv = 1.f / s;
        p1 *= inv; p2 *= inv;
        float n1 = __shfl_down_sync(0xffffffffu, p1, 1);
        float n2 = __shfl_down_sync(0xffffffffu, p2, 1);
        __syncwarp();
        if ((lane & 1) == 0) {
            int j = lane >> 1;
            uint32_t hh, ll;
            split2(make_float2(p1, n1), hh, ll);
            row32[j] = hh; row32[25 + j] = ll;
            if (j <= 8) {
                split2(make_float2(p2, n2), hh, ll);
                row32[16 + j] = hh; row32[41 + j] = ll;
            }
        }
    }
    __syncthreads();

    // ---- ph4: attn@V all heads, sp SPLIT out -> B region ----
    attnv_ps(SC32, Dd, Qh, Ql, warp, lane);
    __syncthreads();

    // ---- ph5: {spatial split in+out -> C (w0-3)} | {qs -> Ee fp32 (w4-7)} ----
    if (warp < 4) gemm2s(Qh, Ql, 3 * FRAG_PER_G, b_ps, 0, Kh, Kl, warp, lane, 1);
    else          gemm2s(Xh, Xl, 4 * FRAG_PER_G, 0, Ee, 0, 0, warp - 4, lane, 0);
    __syncthreads();

    // ---- ph6: ks -> Bb fp32 (8 warps) ----
    gemm_s8(Xh, Xl, 5 * FRAG_PER_G, 0, Bb, warp, lane);
    __syncthreads();

    // ---- ph7: inverse L2 norms ----
    if (tid < 96) {
        float s = 0.f;
        for (int t = 0; t < NTOK; t++) { float v = Ee[t * ST + tid]; s += v * v; }
        NQ[tid] = rsqrtf(fmaxf(s, 1e-24f));
    } else if (tid < 192) {
        int c = tid - 96;
        float s = 0.f;
        for (int t = 0; t < NTOK; t++) { float v = Bb[t * ST + c]; s += v * v; }
        NK[c] = rsqrtf(fmaxf(s, 1e-24f));
    }
    __syncthreads();

    // ---- ph8: cattn raw + normalize ----
    cattn_mma(Ee, Bb, CAT, NQ, NK, warp, lane);
    __syncthreads();
    // ---- ph9: cattn softmax ----
    for (int rid = warp; rid < 96; rid += 8) {
        float* row = CAT + (rid >> 5) * 1088 + (rid & 31) * CST;
        float e = row[lane];
        float m = e;
        #pragma unroll
        for (int o = 16; o > 0; o >>= 1) m = fmaxf(m, __shfl_xor_sync(0xffffffffu, m, o));
        float p = __expf(e - m);
        float s = p;
        #pragma unroll
        for (int o = 16; o > 0; o >>= 1) s += __shfl_xor_sync(0xffffffffu, s, o);
        row[lane] = p * (1.f / s);
    }
    __syncthreads();

    // ---- ph10: xc -> A region SPLIT out ----
    xc_mma_so(CAT, Dd, Xh, Xl, warp, lane);
    __syncthreads();

    // ---- ph11: out_c = xc @ w_pc -> Ee + conv1(v)+GELU -> Bb ----
    gemm_s8(Xh, Xl, 6 * FRAG_PER_G, b_pc, Ee, warp, lane);
    dwconv5(Dd, conv1, Bb, tid, 0);
    __syncthreads();

    // ---- ph12: conv2(gelu) -> Ee += ----
    dwconv5(Bb, conv2, Ee, tid, 1);
    __syncthreads();

    // ---- ph13: final projection, ALL 8 warps: Sa packed (C), Sb fp32 (Ee) ----
    proj8s(Kh, Kl, Ee, b_proj, out + (size_t)blk * (NTOK * NCH), warp, lane);
}

extern "C" void kernel_launch(void* const* d_in, const int* in_sizes, int n_in,
                              void* d_out, int out_size)
{
    const float* x      = (const float*)d_in[0];
    const float* rpb    = (const float*)d_in[1];
    const float* wq     = (const float*)d_in[2];
    const float* bq     = (const float*)d_in[3];
    const float* wk     = (const float*)d_in[4];
    const float* bk     = (const float*)d_in[5];
    const float* wv     = (const float*)d_in[6];
    const float* bv     = (const float*)d_in[7];
    const float* w_ps   = (const float*)d_in[8];
    const float* b_ps   = (const float*)d_in[9];
    const float* wq_sp  = (const float*)d_in[10];
    const float* wk_sp  = (const float*)d_in[11];
    const float* w_pc   = (const float*)d_in[12];
    const float* b_pc   = (const float*)d_in[13];
    const float* conv1  = (const float*)d_in[14];
    const float* conv2  = (const float*)d_in[15];
    const float* w_proj = (const float*)d_in[16];
    const float* b_proj = (const float*)d_in[17];
    float* out = (float*)d_out;

    int nwin = in_sizes[0] / (NTOK * NCH);

    prep_weights<<<(NFRAG + 255) / 256, 256>>>(wq, wk, wv, w_ps, wq_sp, wk_sp, w_pc, w_proj);

    cudaFuncSetAttribute(winattn_kernel,
                         cudaFuncAttributeMaxDynamicSharedMemorySize, SMEM_BYTES);
    winattn_kernel<<<nwin, NTHR, SMEM_BYTES>>>(
        x, rpb, bq, bk, bv, b_ps, b_pc, conv1, conv2, b_proj, out);
}

// round 17
// speedup vs baseline: 1.0399x; 1.0399x over previous
#include <cuda_runtime.h>
#include <math.h>
#include <stdint.h>

// ---------------------------------------------------------------------------
// WindowAttention fused kernel, round 17 (base R15):
//  cattn softmax fused IN-REGISTER into cattn_mma epilogue (quad shfl
//  reductions) -> removes the ph9 phase + one barrier + 24KB smem round-trip.
// ---------------------------------------------------------------------------

#define NTOK   49
#define NCH    96
#define NHEADS 3
#define HDIM   32
#define ST     100
#define PST    50
#define AST    50
#define CST    34
#define SCALEF 0.17677669529663687f
#define NTHR   256

#define BUF     (NTOK*ST)
#define OFF_A   0
#define OFF_B   (OFF_A + BUF)
#define OFF_C   (OFF_B + BUF)
#define OFF_D   (OFF_C + BUF)
#define OFF_RPB (OFF_D + BUF)
#define OFF_NQ  (OFF_RPB + 508)
#define OFF_NK  (OFF_NQ + 96)
#define OFF_E   (OFF_NK + 96)
#define OFF_CAT (OFF_E + BUF)
#define SMEM_FLOATS (OFF_CAT + 3264)
#define SMEM_BYTES  (SMEM_FLOATS * 4)

#define SCRH    2450

#define FRAG_PER_G 2304
#define PROJ_FBASE (7 * FRAG_PER_G)
#define NFRAG      (PROJ_FBASE + 12 * 12 * 32)

__device__ uint4 g_wpack[NFRAG];

typedef unsigned long long u64;

__device__ __forceinline__ void fma2(u64& d, u64 a, u64 b) {
    asm("fma.rn.f32x2 %0,%1,%2,%0;" : "+l"(d) : "l"(a), "l"(b));
}
__device__ __forceinline__ float2 unp(u64 a) {
    float2 r; asm("mov.b64 {%0,%1},%2;" : "=f"(r.x), "=f"(r.y) : "l"(a)); return r;
}
__device__ __forceinline__ u64 lds64(const float* p) {
    return *reinterpret_cast<const u64*>(p);
}
__device__ __forceinline__ uint32_t cvtbf2(float h, float l) {
    uint32_t r; asm("cvt.rn.bf16x2.f32 %0, %1, %2;" : "=r"(r) : "f"(h), "f"(l)); return r;
}
__device__ __forceinline__ float blo2f(uint32_t p) { return __uint_as_float(p << 16); }
__device__ __forceinline__ float bhi2f(uint32_t p) { return __uint_as_float(p & 0xFFFF0000u); }

__device__ __forceinline__ void mma16(float d[4],
                                      uint32_t a0, uint32_t a1, uint32_t a2, uint32_t a3,
                                      uint32_t b0, uint32_t b1) {
    asm volatile("mma.sync.aligned.m16n8k16.row.col.f32.bf16.bf16.f32 "
                 "{%0,%1,%2,%3}, {%4,%5,%6,%7}, {%8,%9}, {%0,%1,%2,%3};"
                 : "+f"(d[0]), "+f"(d[1]), "+f"(d[2]), "+f"(d[3])
                 : "r"(a0), "r"(a1), "r"(a2), "r"(a3), "r"(b0), "r"(b1));
}

__device__ __forceinline__ void split2(float2 p, uint32_t& h, uint32_t& l) {
    h = cvtbf2(p.y, p.x);
    l = cvtbf2(p.y - bhi2f(h), p.x - blo2f(h));
}

// ---------------- prologue: pack weight B-fragments in warp order -----------
__global__ void prep_weights(const float* __restrict__ wq, const float* __restrict__ wk,
                             const float* __restrict__ wv, const float* __restrict__ w_ps,
                             const float* __restrict__ wq_sp, const float* __restrict__ wk_sp,
                             const float* __restrict__ w_pc, const float* __restrict__ w_proj)
{
    int idx = blockIdx.x * 256 + threadIdx.x;
    if (idx >= NFRAG) return;
    const float* Wt[8] = {wq, wk, wv, w_ps, wq_sp, wk_sp, w_pc, w_proj};
    int g, r;
    if (idx < PROJ_FBASE) { g = idx / FRAG_PER_G; r = idx % FRAG_PER_G; }
    else                  { g = 7; r = idx - PROJ_FBASE; }
    int kc   = r / 384;
    int rem  = r % 384;
    int slot = rem / 32;
    int lane = rem % 32;
    int gid = lane >> 2, tig = lane & 3;
    int kp = kc * 8 + tig;
    int n  = slot * 8 + gid;
    const float* W = Wt[g];
    float x0 = W[(2 * kp) * 96 + n];
    float x1 = W[(2 * kp + 1) * 96 + n];
    float y0 = W[(2 * kp + 8) * 96 + n];
    float y1 = W[(2 * kp + 9) * 96 + n];
    uint32_t b0h, b0l, b1h, b1l;
    split2(make_float2(x0, x1), b0h, b0l);
    split2(make_float2(y0, y1), b1h, b1l);
    g_wpack[idx] = make_uint4(b0h, b1h, b0l, b1l);
}

// ---- gemm2s: pre-split A, M=32 x N=48 per slot ------------------------------
__device__ __forceinline__ void gemm2s(const uint32_t* Ah, const uint32_t* Al, int fbase,
                                       const float* __restrict__ bias,
                                       float* Os, uint32_t* Oh, uint32_t* Ol,
                                       int sub, int lane, int splitout)
{
    const int m0 = (sub >> 1) * 32;
    const int nh = sub & 1, n0 = nh * 48;
    const int gid = lane >> 2, tig = lane & 3;
    float d[2][6][4];
    #pragma unroll
    for (int m = 0; m < 2; m++)
        #pragma unroll
        for (int i = 0; i < 6; i++) { d[m][i][0] = d[m][i][1] = d[m][i][2] = d[m][i][3] = 0.f; }
    const int r0b = (m0 + gid) * PST, r1b = (m0 + gid + 8) * PST;
    const int r2b = (m0 + gid + 16) * PST, r3b = (m0 + gid + 24) * PST;
    #pragma unroll
    for (int kc = 0; kc < 6; kc++) {
        const int kp = kc * 8 + tig;
        uint32_t ah[2][4], al[2][4];
        ah[0][0] = Ah[r0b + kp];     al[0][0] = Al[r0b + kp];
        ah[0][1] = Ah[r1b + kp];     al[0][1] = Al[r1b + kp];
        ah[0][2] = Ah[r0b + kp + 4]; al[0][2] = Al[r0b + kp + 4];
        ah[0][3] = Ah[r1b + kp + 4]; al[0][3] = Al[r1b + kp + 4];
        ah[1][0] = Ah[r2b + kp];     al[1][0] = Al[r2b + kp];
        ah[1][1] = Ah[r3b + kp];     al[1][1] = Al[r3b + kp];
        ah[1][2] = Ah[r2b + kp + 4]; al[1][2] = Al[r2b + kp + 4];
        ah[1][3] = Ah[r3b + kp + 4]; al[1][3] = Al[r3b + kp + 4];
        const uint4* Bf = g_wpack + fbase + (kc * 12 + nh * 6) * 32 + lane;
        #pragma unroll
        for (int nt = 0; nt < 6; nt++) {
            uint4 w = Bf[nt * 32];
            #pragma unroll
            for (int m = 0; m < 2; m++) {
                mma16(d[m][nt], ah[m][0], ah[m][1], ah[m][2], ah[m][3], w.x, w.y);
                mma16(d[m][nt], ah[m][0], ah[m][1], ah[m][2], ah[m][3], w.z, w.w);
                mma16(d[m][nt], al[m][0], al[m][1], al[m][2], al[m][3], w.x, w.y);
            }
        }
    }
    #pragma unroll
    for (int m = 0; m < 2; m++) {
        const int r0 = m0 + m * 16 + gid, r1 = r0 + 8;
        #pragma unroll
        for (int nt = 0; nt < 6; nt++) {
            int n = n0 + nt * 8 + tig * 2;
            float bx = 0.f, by = 0.f;
            if (bias) { bx = bias[n]; by = bias[n + 1]; }
            if (splitout) {
                int w = n >> 1;
                if (r0 < NTOK) {
                    uint32_t h, l;
                    split2(make_float2(d[m][nt][0] + bx, d[m][nt][1] + by), h, l);
                    Oh[r0 * PST + w] = h; Ol[r0 * PST + w] = l;
                }
                if (r1 < NTOK) {
                    uint32_t h, l;
                    split2(make_float2(d[m][nt][2] + bx, d[m][nt][3] + by), h, l);
                    Oh[r1 * PST + w] = h; Ol[r1 * PST + w] = l;
                }
            } else {
                if (r0 < NTOK) { float* o = Os + r0 * ST + n; o[0] = d[m][nt][0] + bx; o[1] = d[m][nt][1] + by; }
                if (r1 < NTOK) { float* o = Os + r1 * ST + n; o[0] = d[m][nt][2] + bx; o[1] = d[m][nt][3] + by; }
            }
        }
    }
}

// ---- gemm_s8: pre-split A, 8 warps, M=16 tiles (ks, out_c) -----------------
__device__ __forceinline__ void gemm_s8(const uint32_t* Ah, const uint32_t* Al, int fbase,
                                        const float* __restrict__ bias, float* Os,
                                        int warp, int lane)
{
    const int m0 = (warp >> 1) * 16;
    const int nh = warp & 1, n0 = nh * 48;
    const int gid = lane >> 2, tig = lane & 3;
    float d[6][4];
    #pragma unroll
    for (int i = 0; i < 6; i++) { d[i][0] = d[i][1] = d[i][2] = d[i][3] = 0.f; }
    const int r0b = (m0 + gid) * PST, r1b = (m0 + gid + 8) * PST;
    #pragma unroll
    for (int kc = 0; kc < 6; kc++) {
        const int kp = kc * 8 + tig;
        uint32_t a0h = Ah[r0b + kp],     a0l = Al[r0b + kp];
        uint32_t a1h = Ah[r1b + kp],     a1l = Al[r1b + kp];
        uint32_t a2h = Ah[r0b + kp + 4], a2l = Al[r0b + kp + 4];
        uint32_t a3h = Ah[r1b + kp + 4], a3l = Al[r1b + kp + 4];
        const uint4* Bf = g_wpack + fbase + (kc * 12 + nh * 6) * 32 + lane;
        #pragma unroll
        for (int nt = 0; nt < 6; nt++) {
            uint4 w = Bf[nt * 32];
            mma16(d[nt], a0h, a1h, a2h, a3h, w.x, w.y);
            mma16(d[nt], a0h, a1h, a2h, a3h, w.z, w.w);
            mma16(d[nt], a0l, a1l, a2l, a3l, w.x, w.y);
        }
    }
    const int r0 = m0 + gid, r1 = m0 + gid + 8;
    #pragma unroll
    for (int nt = 0; nt < 6; nt++) {
        int n = n0 + nt * 8 + tig * 2;
        float bx = 0.f, by = 0.f;
        if (bias) { bx = bias[n]; by = bias[n + 1]; }
        if (r0 < NTOK) { float* o = Os + r0 * ST + n; o[0] = d[nt][0] + bx; o[1] = d[nt][1] + by; }
        if (r1 < NTOK) { float* o = Os + r1 * ST + n; o[0] = d[nt][2] + bx; o[1] = d[nt][3] + by; }
    }
}

// ---- final projection: Sa PACKED, Sb fp32, 4 warps, M=32 x N=48 ------------
__device__ __forceinline__ void proj2s(const uint32_t* Sh, const uint32_t* Sl,
                                       const float* Sb,
                                       const float* __restrict__ bias,
                                       float* __restrict__ og, int sub, int lane)
{
    const int m0 = (sub >> 1) * 32;
    const int nh = sub & 1, n0 = nh * 48;
    const int gid = lane >> 2, tig = lane & 3;
    float d[2][6][4];
    #pragma unroll
    for (int m = 0; m < 2; m++)
        #pragma unroll
        for (int i = 0; i < 6; i++) { d[m][i][0] = d[m][i][1] = d[m][i][2] = d[m][i][3] = 0.f; }
    #pragma unroll
    for (int kc = 0; kc < 12; kc++) {
        const int kp = (kc % 6) * 8 + tig;
        uint32_t ah[2][4], al[2][4];
        if (kc < 6) {
            const int r0b = (m0 + gid) * PST, r1b = r0b + 8 * PST;
            const int r2b = r0b + 16 * PST, r3b = r0b + 24 * PST;
            ah[0][0] = Sh[r0b + kp];     al[0][0] = Sl[r0b + kp];
            ah[0][1] = Sh[r1b + kp];     al[0][1] = Sl[r1b + kp];
            ah[0][2] = Sh[r0b + kp + 4]; al[0][2] = Sl[r0b + kp + 4];
            ah[0][3] = Sh[r1b + kp + 4]; al[0][3] = Sl[r1b + kp + 4];
            ah[1][0] = Sh[r2b + kp];     al[1][0] = Sl[r2b + kp];
            ah[1][1] = Sh[r3b + kp];     al[1][1] = Sl[r3b + kp];
            ah[1][2] = Sh[r2b + kp + 4]; al[1][2] = Sl[r2b + kp + 4];
            ah[1][3] = Sh[r3b + kp + 4]; al[1][3] = Sl[r3b + kp + 4];
        } else {
            const float* X0 = Sb + (m0 + gid) * ST;
            const float* X1 = X0 + 8 * ST;
            const float* X2 = X0 + 16 * ST;
            const float* X3 = X0 + 24 * ST;
            split2(*reinterpret_cast<const float2*>(X0 + 2 * kp),     ah[0][0], al[0][0]);
            split2(*reinterpret_cast<const float2*>(X1 + 2 * kp),     ah[0][1], al[0][1]);
            split2(*reinterpret_cast<const float2*>(X0 + 2 * kp + 8), ah[0][2], al[0][2]);
            split2(*reinterpret_cast<const float2*>(X1 + 2 * kp + 8), ah[0][3], al[0][3]);
            split2(*reinterpret_cast<const float2*>(X2 + 2 * kp),     ah[1][0], al[1][0]);
            split2(*reinterpret_cast<const float2*>(X3 + 2 * kp),     ah[1][1], al[1][1]);
            split2(*reinterpret_cast<const float2*>(X2 + 2 * kp + 8), ah[1][2], al[1][2]);
            split2(*reinterpret_cast<const float2*>(X3 + 2 * kp + 8), ah[1][3], al[1][3]);
        }
        const uint4* Bf = g_wpack + PROJ_FBASE + (kc * 12 + nh * 6) * 32 + lane;
        #pragma unroll
        for (int nt = 0; nt < 6; nt++) {
            uint4 w = Bf[nt * 32];
            #pragma unroll
            for (int m = 0; m < 2; m++) {
                mma16(d[m][nt], ah[m][0], ah[m][1], ah[m][2], ah[m][3], w.x, w.y);
                mma16(d[m][nt], ah[m][0], ah[m][1], ah[m][2], ah[m][3], w.z, w.w);
                mma16(d[m][nt], al[m][0], al[m][1], al[m][2], al[m][3], w.x, w.y);
            }
        }
    }
    #pragma unroll
    for (int m = 0; m < 2; m++) {
        const int r0 = m0 + m * 16 + gid, r1 = r0 + 8;
        #pragma unroll
        for (int nt = 0; nt < 6; nt++) {
            int n = n0 + nt * 8 + tig * 2;
            float bx = bias[n], by = bias[n + 1];
            if (r0 < NTOK) {
                float2 v = make_float2(d[m][nt][0] + bx, d[m][nt][1] + by);
                *reinterpret_cast<float2*>(og + r0 * NCH + n) = v;
            }
            if (r1 < NTOK) {
                float2 v = make_float2(d[m][nt][2] + bx, d[m][nt][3] + by);
                *reinterpret_cast<float2*>(og + r1 * NCH + n) = v;
            }
        }
    }
}

// ---- scores from PRE-SPLIT q/k ----------------------------------------------
__device__ __forceinline__ void scores_mma_s(const uint32_t* Qh, const uint32_t* Ql,
                                             const uint32_t* Kh, const uint32_t* Kl,
                                             float* SC, const float* RPB,
                                             int slot0, int stride, int lane)
{
    const int gid = lane >> 2, tig = lane & 3;
    for (int slot = slot0; slot < 24; slot += stride) {
        const int h = slot >> 3, q = slot & 7;
        const int m0 = (q >> 1) * 16, n0 = (q & 1) * 32;
        const int cw = h * 16;
        float* SCR = SC + h * SCRH;
        float d[4][4];
        #pragma unroll
        for (int i = 0; i < 4; i++) { d[i][0] = d[i][1] = d[i][2] = d[i][3] = 0.f; }
        const int q0b = (m0 + gid) * PST + cw, q1b = q0b + 8 * PST;
        #pragma unroll
        for (int kc = 0; kc < 2; kc++) {
            const int kp = kc * 8 + tig;
            uint32_t a0h = Qh[q0b + kp],     a0l = Ql[q0b + kp];
            uint32_t a1h = Qh[q1b + kp],     a1l = Ql[q1b + kp];
            uint32_t a2h = Qh[q0b + kp + 4], a2l = Ql[q0b + kp + 4];
            uint32_t a3h = Qh[q1b + kp + 4], a3l = Ql[q1b + kp + 4];
            #pragma unroll
            for (int nt = 0; nt < 4; nt++) {
                const int kb = (n0 + nt * 8 + gid) * PST + cw;
                uint32_t b0h = Kh[kb + kp],     b0l = Kl[kb + kp];
                uint32_t b1h = Kh[kb + kp + 4], b1l = Kl[kb + kp + 4];
                mma16(d[nt], a0h, a1h, a2h, a3h, b0h, b1h);
                mma16(d[nt], a0h, a1h, a2h, a3h, b0l, b1l);
                mma16(d[nt], a0l, a1l, a2l, a3l, b0h, b1h);
            }
        }
        const int r0 = m0 + gid, r1 = r0 + 8;
        const int i0r = r0 / 7, i0c = r0 % 7;
        const int i1r = r1 / 7, i1c = r1 % 7;
        #pragma unroll
        for (int nt = 0; nt < 4; nt++) {
            #pragma unroll
            for (int c = 0; c < 2; c++) {
                int j = n0 + nt * 8 + tig * 2 + c;
                if (j < NTOK) {
                    int jr = j / 7, jc = j % 7;
                    if (r0 < NTOK)
                        SCR[r0 * AST + j] = d[nt][c] * SCALEF
                            + RPB[((i0r - jr + 6) * 13 + (i0c - jc + 6)) * 3 + h];
                    if (r1 < NTOK)
                        SCR[r1 * AST + j] = d[nt][2 + c] * SCALEF
                            + RPB[((i1r - jr + 6) * 13 + (i1c - jc + 6)) * 3 + h];
                }
            }
        }
    }
}

// ---- attn@V from PRE-SPLIT P; sp written PRE-SPLIT --------------------------
__device__ __forceinline__ void attnv_ps(const uint32_t* SC32, const float* V,
                                         uint32_t* SPh, uint32_t* SPl,
                                         int warp, int lane)
{
    const int gid = lane >> 2, tig = lane & 3;
    for (int slot = warp; slot < 24; slot += 8) {
        const int h = slot >> 3, q = slot & 7;
        const int m0 = (q >> 1) * 16, n0 = (q & 1) * 16;
        const int ch0 = h * HDIM;
        const uint32_t* Pb = SC32 + h * SCRH;
        float d[2][4];
        #pragma unroll
        for (int i = 0; i < 2; i++) { d[i][0] = d[i][1] = d[i][2] = d[i][3] = 0.f; }
        const int r0w = (m0 + gid) * AST, r1w = r0w + 8 * AST;
        #pragma unroll
        for (int kc = 0; kc < 4; kc++) {
            const int w0 = kc * 8 + tig;
            const int w2 = w0 + 4;
            const int k0 = 2 * w0, k2 = 2 * w2;
            uint32_t a0h = 0, a0l = 0, a1h = 0, a1l = 0;
            uint32_t a2h = 0, a2l = 0, a3h = 0, a3l = 0;
            if (w0 <= 24) {
                a0h = Pb[r0w + w0]; a0l = Pb[r0w + 25 + w0];
                a1h = Pb[r1w + w0]; a1l = Pb[r1w + 25 + w0];
            }
            if (w2 <= 24) {
                a2h = Pb[r0w + w2]; a2l = Pb[r0w + 25 + w2];
                a3h = Pb[r1w + w2]; a3l = Pb[r1w + 25 + w2];
            }
            #pragma unroll
            for (int nt = 0; nt < 2; nt++) {
                const int n = ch0 + n0 + nt * 8 + gid;
                uint32_t b0h, b0l, b1h, b1l;
                split2(make_float2(V[k0 * ST + n], V[(k0 + 1) * ST + n]), b0h, b0l);
                split2(make_float2(V[k2 * ST + n], V[(k2 + 1) * ST + n]), b1h, b1l);
                mma16(d[nt], a0h, a1h, a2h, a3h, b0h, b1h);
                mma16(d[nt], a0h, a1h, a2h, a3h, b0l, b1l);
                mma16(d[nt], a0l, a1l, a2l, a3l, b0h, b1h);
            }
        }
        const int r0 = m0 + gid, r1 = r0 + 8;
        #pragma unroll
        for (int nt = 0; nt < 2; nt++) {
            int n = ch0 + n0 + nt * 8 + tig * 2;
            int w = n >> 1;
            if (r0 < NTOK) {
                uint32_t hh, ll;
                split2(make_float2(d[nt][0], d[nt][1]), hh, ll);
                SPh[r0 * PST + w] = hh; SPl[r0 * PST + w] = ll;
            }
            if (r1 < NTOK) {
                uint32_t hh, ll;
                split2(make_float2(d[nt][2], d[nt][3]), hh, ll);
                SPh[r1 * PST + w] = hh; SPl[r1 * PST + w] = ll;
            }
        }
    }
}

// ---- cattn via MMA (6 warps) with FUSED in-register softmax ----------------
// After the MMA, each output row's 32 e-values live in one quad (4 lanes,
// 8 regs each): reduce max/sum with shfl_xor(1,2), write final probs only.
__device__ __forceinline__ void cattn_mma(const float* QS, const float* KS,
                                          float* CAT, const float* NQ, const float* NK,
                                          int warp, int lane)
{
    if (warp >= 6) return;
    const int h = warp >> 1, mt = warp & 1;
    const int ch = h * HDIM, m0 = mt * 16;
    const int gid = lane >> 2, tig = lane & 3;
    float d[4][4];
    #pragma unroll
    for (int i = 0; i < 4; i++) { d[i][0] = d[i][1] = d[i][2] = d[i][3] = 0.f; }
    #pragma unroll
    for (int kc = 0; kc < 4; kc++) {
        const int k0 = 2 * (kc * 8 + tig);
        const int k1 = k0 + 1, k2 = k0 + 8, k3 = k0 + 9;
        const int ca = ch + m0 + gid;
        float a00 = (k0 < NTOK) ? KS[k0 * ST + ca] : 0.f;
        float a01 = (k1 < NTOK) ? KS[k1 * ST + ca] : 0.f;
        float a10 = (k0 < NTOK) ? KS[k0 * ST + ca + 8] : 0.f;
        float a11 = (k1 < NTOK) ? KS[k1 * ST + ca + 8] : 0.f;
        float a20 = (k2 < NTOK) ? KS[k2 * ST + ca] : 0.f;
        float a21 = (k3 < NTOK) ? KS[k3 * ST + ca] : 0.f;
        float a30 = (k2 < NTOK) ? KS[k2 * ST + ca + 8] : 0.f;
        float a31 = (k3 < NTOK) ? KS[k3 * ST + ca + 8] : 0.f;
        uint32_t a0h, a0l, a1h, a1l, a2h, a2l, a3h, a3l;
        split2(make_float2(a00, a01), a0h, a0l);
        split2(make_float2(a10, a11), a1h, a1l);
        split2(make_float2(a20, a21), a2h, a2l);
        split2(make_float2(a30, a31), a3h, a3l);
        #pragma unroll
        for (int nt = 0; nt < 4; nt++) {
            const int ce = ch + nt * 8 + gid;
            float b00 = (k0 < NTOK) ? QS[k0 * ST + ce] : 0.f;
            float b01 = (k1 < NTOK) ? QS[k1 * ST + ce] : 0.f;
            float b10 = (k2 < NTOK) ? QS[k2 * ST + ce] : 0.f;
            float b11 = (k3 < NTOK) ? QS[k3 * ST + ce] : 0.f;
            uint32_t b0h, b0l, b1h, b1l;
            split2(make_float2(b00, b01), b0h, b0l);
            split2(make_float2(b10, b11), b1h, b1l);
            mma16(d[nt], a0h, a1h, a2h, a3h, b0h, b1h);
            mma16(d[nt], a0h, a1h, a2h, a3h, b0l, b1l);
            mma16(d[nt], a0l, a1l, a2l, a3l, b0h, b1h);
        }
    }
    const int r0 = m0 + gid, r1 = r0 + 8;
    const float sk0 = NK[ch + r0] * SCALEF;
    const float sk1 = NK[ch + r1] * SCALEF;
    // normalized logits in registers: v0/v1[nt*2+c] for e = nt*8 + tig*2 + c
    float v0[8], v1[8];
    #pragma unroll
    for (int nt = 0; nt < 4; nt++) {
        #pragma unroll
        for (int c = 0; c < 2; c++) {
            int e0 = nt * 8 + tig * 2 + c;
            float q = NQ[ch + e0];
            v0[nt * 2 + c] = d[nt][c]     * sk0 * q;
            v1[nt * 2 + c] = d[nt][2 + c] * sk1 * q;
        }
    }
    // quad-local softmax (each row's 32 values live in 4 lanes x 8 regs)
    float m0v = v0[0], m1v = v1[0];
    #pragma unroll
    for (int i = 1; i < 8; i++) { m0v = fmaxf(m0v, v0[i]); m1v = fmaxf(m1v, v1[i]); }
    #pragma unroll
    for (int o = 1; o <= 2; o <<= 1) {
        m0v = fmaxf(m0v, __shfl_xor_sync(0xffffffffu, m0v, o));
        m1v = fmaxf(m1v, __shfl_xor_sync(0xffffffffu, m1v, o));
    }
    float s0 = 0.f, s1 = 0.f;
    #pragma unroll
    for (int i = 0; i < 8; i++) {
        v0[i] = __expf(v0[i] - m0v); s0 += v0[i];
        v1[i] = __expf(v1[i] - m1v); s1 += v1[i];
    }
    #pragma unroll
    for (int o = 1; o <= 2; o <<= 1) {
        s0 += __shfl_xor_sync(0xffffffffu, s0, o);
        s1 += __shfl_xor_sync(0xffffffffu, s1, o);
    }
    float i0 = 1.f / s0, i1 = 1.f / s1;
    float* C0 = CAT + h * 1088 + r0 * CST;
    float* C1 = CAT + h * 1088 + r1 * CST;
    #pragma unroll
    for (int nt = 0; nt < 4; nt++) {
        int e0 = nt * 8 + tig * 2;
        C0[e0]     = v0[nt * 2]     * i0;
        C0[e0 + 1] = v0[nt * 2 + 1] * i0;
        C1[e0]     = v1[nt * 2]     * i1;
        C1[e0 + 1] = v1[nt * 2 + 1] * i1;
    }
}

// ---- xc via MMA, output PRE-SPLIT -------------------------------------------
__device__ __forceinline__ void xc_mma_so(const float* CAT, const float* V,
                                          uint32_t* Oh, uint32_t* Ol,
                                          int warp, int lane)
{
    const int gid = lane >> 2, tig = lane & 3;
    for (int slot = warp; slot < 12; slot += 8) {
        const int h = slot >> 2, mt = slot & 3;
        const int ch = h * HDIM, m0 = mt * 16;
        float d[4][4];
        #pragma unroll
        for (int i = 0; i < 4; i++) { d[i][0] = d[i][1] = d[i][2] = d[i][3] = 0.f; }
        const float* Ar0 = V + (m0 + gid) * ST + ch;
        const float* Ar1 = Ar0 + 8 * ST;
        #pragma unroll
        for (int kc = 0; kc < 2; kc++) {
            const int kp = kc * 8 + tig;
            uint32_t a0h, a0l, a1h, a1l, a2h, a2l, a3h, a3l;
            split2(*reinterpret_cast<const float2*>(Ar0 + 2 * kp), a0h, a0l);
            split2(*reinterpret_cast<const float2*>(Ar1 + 2 * kp), a1h, a1l);
            split2(*reinterpret_cast<const float2*>(Ar0 + 2 * kp + 8), a2h, a2l);
            split2(*reinterpret_cast<const float2*>(Ar1 + 2 * kp + 8), a3h, a3l);
            #pragma unroll
            for (int nt = 0; nt < 4; nt++) {
                const float* Br = CAT + h * 1088 + (nt * 8 + gid) * CST;
                uint32_t b0h, b0l, b1h, b1l;
                split2(*reinterpret_cast<const float2*>(Br + 2 * kp), b0h, b0l);
                split2(*reinterpret_cast<const float2*>(Br + 2 * kp + 8), b1h, b1l);
                mma16(d[nt], a0h, a1h, a2h, a3h, b0h, b1h);
                mma16(d[nt], a0h, a1h, a2h, a3h, b0l, b1l);
                mma16(d[nt], a0l, a1l, a2l, a3l, b0h, b1h);
            }
        }
        const int r0 = m0 + gid, r1 = r0 + 8;
        #pragma unroll
        for (int nt = 0; nt < 4; nt++) {
            int n = ch + nt * 8 + tig * 2;
            int w = n >> 1;
            if (r0 < NTOK) {
                uint32_t hh, ll;
                split2(make_float2(d[nt][0], d[nt][1]), hh, ll);
                Oh[r0 * PST + w] = hh; Ol[r0 * PST + w] = ll;
            }
            if (r1 < NTOK) {
                uint32_t hh, ll;
                split2(make_float2(d[nt][2], d[nt][3]), hh, ll);
                Oh[r1 * PST + w] = hh; Ol[r1 * PST + w] = ll;
            }
        }
    }
}

// ---- depthwise 3x3 conv -----------------------------------------------------
__device__ __forceinline__ void dwconv5(const float* In, const float* __restrict__ Wc,
                                        float* Out, int tid, int mode)
{
    if (tid >= 240) return;
    const int c0 = (tid / 10) * 4, t0 = (tid % 10) * 5;
    u64 wc[9][2];
    #pragma unroll
    for (int s = 0; s < 9; s++) {
        const ulonglong2* wp = reinterpret_cast<const ulonglong2*>(Wc + s * 96 + c0);
        ulonglong2 w = *wp;
        wc[s][0] = w.x; wc[s][1] = w.y;
    }
    #pragma unroll
    for (int tt = 0; tt < 5; tt++) {
        int t = t0 + tt;
        if (t >= NTOK) break;
        int r = t / 7, cc = t % 7;
        u64 a0 = 0ULL, a1 = 0ULL;
        #pragma unroll
        for (int dr = 0; dr < 3; dr++) {
            int rr = r + dr - 1;
            if (rr < 0 || rr > 6) continue;
            #pragma unroll
            for (int dc = 0; dc < 3; dc++) {
                int c2 = cc + dc - 1;
                if (c2 < 0 || c2 > 6) continue;
                const float* vp = In + (rr * 7 + c2) * ST + c0;
                fma2(a0, lds64(vp), wc[dr * 3 + dc][0]);
                fma2(a1, lds64(vp + 2), wc[dr * 3 + dc][1]);
            }
        }
        float2 p0 = unp(a0), p1 = unp(a1);
        float* o = Out + t * ST + c0;
        if (mode == 0) {
            o[0] = 0.5f * p0.x * (1.f + erff(p0.x * 0.70710678118654752f));
            o[1] = 0.5f * p0.y * (1.f + erff(p0.y * 0.70710678118654752f));
            o[2] = 0.5f * p1.x * (1.f + erff(p1.x * 0.70710678118654752f));
            o[3] = 0.5f * p1.y * (1.f + erff(p1.y * 0.70710678118654752f));
        } else {
            o[0] += p0.x; o[1] += p0.y; o[2] += p1.x; o[3] += p1.y;
        }
    }
}

__global__ __launch_bounds__(NTHR, 2) void winattn_kernel(
    const float* __restrict__ x,
    const float* __restrict__ rpb_table,
    const float* __restrict__ bq,  const float* __restrict__ bk,
    const float* __restrict__ bv,  const float* __restrict__ b_ps,
    const float* __restrict__ b_pc,
    const float* __restrict__ conv1, const float* __restrict__ conv2,
    const float* __restrict__ b_proj,
    float* __restrict__ out)
{
    extern __shared__ float sm[];
    uint32_t* Xh = reinterpret_cast<uint32_t*>(sm + OFF_A);
    uint32_t* Xl = Xh + 2450;
    uint32_t* Qh = reinterpret_cast<uint32_t*>(sm + OFF_B);
    uint32_t* Ql = Qh + 2450;
    float*    Bb = sm + OFF_B;
    uint32_t* Kh = reinterpret_cast<uint32_t*>(sm + OFF_C);
    uint32_t* Kl = Kh + 2450;
    float* Dd  = sm + OFF_D;
    float* Ee  = sm + OFF_E;
    uint32_t* SC32 = reinterpret_cast<uint32_t*>(Ee);
    float* RPB = sm + OFF_RPB;
    float* NQ  = sm + OFF_NQ;
    float* NK  = sm + OFF_NK;
    float* CAT = sm + OFF_CAT;

    const int tid  = threadIdx.x;
    const int blk  = blockIdx.x;
    const int warp = tid >> 5, lane = tid & 31;

    {
        const float4* xg4 = reinterpret_cast<const float4*>(x + (size_t)blk * (NTOK * NCH));
        for (int i4 = tid; i4 < NTOK * 24; i4 += NTHR) {
            float4 v = xg4[i4];
            int t = i4 / 24, p = (i4 % 24) * 2;
            uint32_t h0, l0, h1, l1;
            split2(make_float2(v.x, v.y), h0, l0);
            split2(make_float2(v.z, v.w), h1, l1);
            Xh[t * PST + p] = h0;     Xl[t * PST + p] = l0;
            Xh[t * PST + p + 1] = h1; Xl[t * PST + p + 1] = l1;
        }
        for (int i = tid; i < 507; i += NTHR) RPB[i] = rpb_table[i];
    }
    __syncthreads();

    // ---- ph1: {q (w0-3) | k (w4-7)}, split in + SPLIT out ----
    if (warp < 4) gemm2s(Xh, Xl, 0 * FRAG_PER_G, bq, 0, Qh, Ql, warp, lane, 1);
    else          gemm2s(Xh, Xl, 1 * FRAG_PER_G, bk, 0, Kh, Kl, warp - 4, lane, 1);
    __syncthreads();

    // ---- ph2: {v (w0-3, fp32 out) | scores all heads (w4-7)} ----
    if (warp < 4) gemm2s(Xh, Xl, 2 * FRAG_PER_G, bv, Dd, 0, 0, warp, lane, 0);
    else          scores_mma_s(Qh, Ql, Kh, Kl, Ee, RPB, warp - 4, 4, lane);
    __syncthreads();

    // ---- ph3: softmax + in-place P packing ----
    for (int r = warp; r < 3 * NTOK; r += 8) {
        float* row = Ee + (r / NTOK) * SCRH + (r % NTOK) * AST;
        uint32_t* row32 = reinterpret_cast<uint32_t*>(row);
        float e1 = row[lane];
        bool hi = (lane + 32) < NTOK;
        float e2 = hi ? row[lane + 32] : -3.4e38f;
        float m = fmaxf(e1, e2);
        #pragma unroll
        for (int o = 16; o > 0; o >>= 1) m = fmaxf(m, __shfl_xor_sync(0xffffffffu, m, o));
        float p1 = __expf(e1 - m);
        float p2 = hi ? __expf(e2 - m) : 0.f;
        float s = p1 + p2;
        #pragma unroll
        for (int o = 16; o > 0; o >>= 1) s += __shfl_xor_sync(0xffffffffu, s, o);
        float inv = 1.f / s;
        p1 *= inv; p2 *= inv;
        float n1 = __shfl_down_sync(0xffffffffu, p1, 1);
        float n2 = __shfl_down_sync(0xffffffffu, p2, 1);
        __syncwarp();
        if ((lane & 1) == 0) {
            int j = lane >> 1;
            uint32_t hh, ll;
            split2(make_float2(p1, n1), hh, ll);
            row32[j] = hh; row32[25 + j] = ll;
            if (j <= 8) {
                split2(make_float2(p2, n2), hh, ll);
                row32[16 + j] = hh; row32[41 + j] = ll;
            }
        }
    }
    __syncthreads();

    // ---- ph4: attn@V all heads, sp SPLIT out -> B region ----
    attnv_ps(SC32, Dd, Qh, Ql, warp, lane);
    __syncthreads();

    // ---- ph5: {spatial split in+out -> C (w0-3)} | {qs -> Ee fp32 (w4-7)} ----
    if (warp < 4) gemm2s(Qh, Ql, 3 * FRAG_PER_G, b_ps, 0, Kh, Kl, warp, lane, 1);
    else          gemm2s(Xh, Xl, 4 * FRAG_PER_G, 0, Ee, 0, 0, warp - 4, lane, 0);
    __syncthreads();

    // ---- ph6: ks -> Bb fp32 (8 warps) ----
    gemm_s8(Xh, Xl, 5 * FRAG_PER_G, 0, Bb, warp, lane);
    __syncthreads();

    // ---- ph7: inverse L2 norms ----
    if (tid < 96) {
        float s = 0.f;
        for (int t = 0; t < NTOK; t++) { float v = Ee[t * ST + tid]; s += v * v; }
        NQ[tid] = rsqrtf(fmaxf(s, 1e-24f));
    } else if (tid < 192) {
        int c = tid - 96;
        float s = 0.f;
        for (int t = 0; t < NTOK; t++) { float v = Bb[t * ST + c]; s += v * v; }
        NK[c] = rsqrtf(fmaxf(s, 1e-24f));
    }
    __syncthreads();

    // ---- ph8: cattn + FUSED softmax (writes final probs to CAT) ----
    cattn_mma(Ee, Bb, CAT, NQ, NK, warp, lane);
    __syncthreads();

    // ---- ph9: xc -> A region SPLIT out ----
    xc_mma_so(CAT, Dd, Xh, Xl, warp, lane);
    __syncthreads();

    // ---- ph10: out_c = xc @ w_pc -> Ee + conv1(v)+GELU -> Bb ----
    gemm_s8(Xh, Xl, 6 * FRAG_PER_G, b_pc, Ee, warp, lane);
    dwconv5(Dd, conv1, Bb, tid, 0);
    __syncthreads();

    // ---- ph11: conv2(gelu) -> Ee += ----
    dwconv5(Bb, conv2, Ee, tid, 1);
    __syncthreads();

    // ---- ph12: final projection (warps 0-3): Sa packed (C), Sb fp32 (Ee) ----
    if (warp < 4)
        proj2s(Kh, Kl, Ee, b_proj, out + (size_t)blk * (NTOK * NCH), warp, lane);
}

extern "C" void kernel_launch(void* const* d_in, const int* in_sizes, int n_in,
                              void* d_out, int out_size)
{
    const float* x      = (const float*)d_in[0];
    const float* rpb    = (const float*)d_in[1];
    const float* wq     = (const float*)d_in[2];
    const float* bq     = (const float*)d_in[3];
    const float* wk     = (const float*)d_in[4];
    const float* bk     = (const float*)d_in[5];
    const float* wv     = (const float*)d_in[6];
    const float* bv     = (const float*)d_in[7];
    const float* w_ps   = (const float*)d_in[8];
    const float* b_ps   = (const float*)d_in[9];
    const float* wq_sp  = (const float*)d_in[10];
    const float* wk_sp  = (const float*)d_in[11];
    const float* w_pc   = (const float*)d_in[12];
    const float* b_pc   = (const float*)d_in[13];
    const float* conv1  = (const float*)d_in[14];
    const float* conv2  = (const float*)d_in[15];
    const float* w_proj = (const float*)d_in[16];
    const float* b_proj = (const float*)d_in[17];
    float* out = (float*)d_out;

    int nwin = in_sizes[0] / (NTOK * NCH);

    prep_weights<<<(NFRAG + 255) / 256, 256>>>(wq, wk, wv, w_ps, wq_sp, wk_sp, w_pc, w_proj);

    cudaFuncSetAttribute(winattn_kernel,
                         cudaFuncAttributeMaxDynamicSharedMemorySize, SMEM_BYTES);
    winattn_kernel<<<nwin, NTHR, SMEM_BYTES>>>(
        x, rpb, bq, bk, bv, b_ps, b_pc, conv1, conv2, b_proj, out);
}